// round 12
// baseline (speedup 1.0000x reference)
#include <cuda_runtime.h>
#include <math.h>

#define BB 8
#define LL 1536
#define HH 8
#define EE 64
#define HE 512          // H*E
#define BHE 4096        // B*H*E
#define TOPK 7          // int(log(1536)) = 7

// ---------------- scratch (static __device__, no allocation) ----------------
__device__ float g_qr[(size_t)BHE * LL];   // layernormed q, (b,h,e,l)
__device__ float g_kr[(size_t)BHE * LL];   // layernormed k, (b,h,e,l)
__device__ float g_mean[BB * LL];          // sum over (h,e) of clipped corr
__device__ float g_scal[4];                // [0]=sigmoid(freq), [1..3]=softmax(scale_weights)
__device__ int   g_delays[BB * TOPK];
__device__ float g_nw[BB * TOPK];

// ---------------- K1: LayerNorm over E + transpose; block(0,0,0) also inits ----
__global__ __launch_bounds__(256) void k1_ln(const float* __restrict__ q,
                                             const float* __restrict__ kk,
                                             const float* __restrict__ sw,
                                             const float* __restrict__ ff) {
    __shared__ float tile[32][EE + 1];
    __shared__ float mu[32], isd[32];
    int tid = threadIdx.x;
    if (blockIdx.x == 0 && blockIdx.y == 0 && blockIdx.z == 0) {
        for (int i = tid; i < BB * LL; i += 256) g_mean[i] = 0.f;
        if (tid == 0) {
            g_scal[0] = 1.f / (1.f + expf(-ff[0]));
            float a = sw[0], b = sw[1], c = sw[2];
            float mx = fmaxf(a, fmaxf(b, c));
            float ea = expf(a - mx), eb = expf(b - mx), ec = expf(c - mx);
            float s = ea + eb + ec;
            g_scal[1] = ea / s; g_scal[2] = eb / s; g_scal[3] = ec / s;
        }
    }
    int l0 = blockIdx.x * 32;
    int bh = blockIdx.y;                 // b*8 + h
    int b  = bh >> 3, h = bh & 7;
    const float* in = blockIdx.z ? kk : q;
    float* out      = blockIdx.z ? g_kr : g_qr;
    int e = tid & 63, r0 = tid >> 6;
    for (int r = r0; r < 32; r += 4)
        tile[r][e] = in[(((size_t)b * LL + l0 + r) * HH + h) * EE + e];
    __syncthreads();
    int lane = tid & 31, w = tid >> 5;
    for (int r = w; r < 32; r += 8) {
        float x0 = tile[r][lane], x1 = tile[r][lane + 32];
        float s = x0 + x1, s2 = x0 * x0 + x1 * x1;
        #pragma unroll
        for (int off = 16; off; off >>= 1) {
            s  += __shfl_down_sync(0xffffffffu, s,  off);
            s2 += __shfl_down_sync(0xffffffffu, s2, off);
        }
        if (lane == 0) {
            float m = s * (1.f / EE);
            float v = s2 * (1.f / EE) - m * m;
            mu[r] = m; isd[r] = rsqrtf(v + 1e-5f);
        }
    }
    __syncthreads();
    int li = tid & 31, e0 = tid >> 5;
    for (int ee = e0; ee < EE; ee += 8) {
        float val = (tile[li][ee] - mu[li]) * isd[li];
        out[(((size_t)bh) * EE + ee) * LL + l0 + li] = val;
    }
}

// ---------------- FFT: Stockham + conflict-free tail fusion, AoS float2 ------
// tw[t] = exp(-2*pi*i*t/1536), t in [0,1024).

__device__ __forceinline__ float2 cmul(float2 a, float2 b) {
    return make_float2(a.x * b.x - a.y * b.y, a.x * b.y + a.y * b.x);
}

// DIF butterfly of radix R, post-multiplying slot q by w^q (w2 = w^2).
template<int R>
__device__ __forceinline__ void bfly(float2* x, float2 w1, float2 w2) {
    if (R == 4) {
        float t0r = x[0].x + x[2].x, t0i = x[0].y + x[2].y;
        float t1r = x[0].x - x[2].x, t1i = x[0].y - x[2].y;
        float t2r = x[1].x + x[3].x, t2i = x[1].y + x[3].y;
        float t3r = x[1].x - x[3].x, t3i = x[1].y - x[3].y;
        float2 d1 = make_float2(t1r + t3i, t1i - t3r);   // t1 - i*t3
        float2 d2 = make_float2(t0r - t2r, t0i - t2i);
        float2 d3 = make_float2(t1r - t3i, t1i + t3r);   // t1 + i*t3
        x[0] = make_float2(t0r + t2r, t0i + t2i);
        x[1] = cmul(d1, w1);
        x[2] = cmul(d2, w2);
        x[3] = cmul(d3, cmul(w1, w2));
    } else if (R == 3) {
        float t1r = x[1].x + x[2].x, t1i = x[1].y + x[2].y;
        float ur  = x[0].x - 0.5f * t1r, ui = x[0].y - 0.5f * t1i;
        const float s3 = 0.8660254037844386f;
        float vr = s3 * (x[1].x - x[2].x), vi = s3 * (x[1].y - x[2].y);
        float2 d1 = make_float2(ur + vi, ui - vr);       // u - i*v
        float2 d2 = make_float2(ur - vi, ui + vr);       // u + i*v
        x[0] = make_float2(x[0].x + t1r, x[0].y + t1i);
        x[1] = cmul(d1, w1);
        x[2] = cmul(d2, w2);
    } else {  // R == 2
        float2 d1 = make_float2(x[0].x - x[1].x, x[0].y - x[1].y);
        x[0] = make_float2(x[0].x + x[1].x, x[0].y + x[1].y);
        x[1] = cmul(d1, w1);
    }
}

// Single Stockham stage.
template<int R, int M, int L>
__device__ __forceinline__ void fstage(const float2* __restrict__ a,
                                       float2* __restrict__ b,
                                       const float2* __restrict__ tw, int tid) {
    constexpr int NB   = L * M;
    constexpr int STEP = 1536 / (R * L);
    for (int t = tid; t < NB; t += 256) {
        int j = t / M;
        int k = t - j * M;
        float2 x[R];
        #pragma unroll
        for (int q = 0; q < R; q++) x[q] = a[t + q * NB];
        float2 w1 = tw[j * STEP];
        float2 w2;
        if (R > 2) w2 = tw[2 * j * STEP]; else w2 = make_float2(1.f, 0.f);
        bfly<R>(x, w1, w2);
        #pragma unroll
        for (int q = 0; q < R; q++) b[k + M * (q + R * j)] = x[q];
    }
    __syncthreads();
}

// Fused pair of Stockham stages (validated in R10): A=(R1,M,LA) then
// B=(R2, R1*M, LA/R2), intermediate in registers. Used ONLY where the
// store pattern is conflict-free (M >= 48, or tiny tail passes).
template<int R1, int R2, int M, int LA>
__device__ __forceinline__ void ffstage(const float2* __restrict__ a,
                                        float2* __restrict__ c,
                                        const float2* __restrict__ tw, int tid) {
    constexpr int LB    = LA / R2;
    constexpr int NBA   = LA * M;
    constexpr int UNITS = M * LB;
    constexpr int STEPA = 1536 / (R1 * LA);
    constexpr int STEPB = 1536 / (R2 * LB);
    for (int u = tid; u < UNITS; u += 256) {
        int jp = u / M;
        int k  = u - jp * M;
        float2 y[R2][R1];
        #pragma unroll
        for (int qp = 0; qp < R2; qp++) {
            int j = jp + qp * LB;
            float2 x[R1];
            #pragma unroll
            for (int q = 0; q < R1; q++) x[q] = a[k + M * j + q * NBA];
            float2 wa1 = tw[j * STEPA];
            float2 wa2;
            if (R1 > 2) wa2 = tw[2 * j * STEPA]; else wa2 = make_float2(1.f, 0.f);
            bfly<R1>(x, wa1, wa2);
            #pragma unroll
            for (int q = 0; q < R1; q++) y[qp][q] = x[q];
        }
        float2 wb1 = tw[jp * STEPB];
        float2 wb2;
        if (R2 > 2) wb2 = tw[2 * jp * STEPB]; else wb2 = make_float2(1.f, 0.f);
        #pragma unroll
        for (int qt = 0; qt < R1; qt++) {
            float2 xx[R2];
            #pragma unroll
            for (int qp = 0; qp < R2; qp++) xx[qp] = y[qp][qt];
            bfly<R2>(xx, wb1, wb2);
            #pragma unroll
            for (int p = 0; p < R2; p++)
                c[k + M * qt + (R1 * M) * (p + R2 * jp)] = xx[p];
        }
    }
    __syncthreads();
}

// fft1536(A,B): 5 passes (tail pair fused), result in B.
__device__ __forceinline__ void fft1536(float2* x, float2* y, const float2* tw, int tid) {
    fstage<3, 1,  512>(x, y, tw, tid);
    fstage<4, 3,  128>(y, x, tw, tid);
    fstage<4, 12, 32 >(x, y, tw, tid);
    ffstage<4, 4, 48, 8>(y, x, tw, tid);     // (4,48,8)+(4,192,2), conflict-free
    fstage<2, 768, 1 >(x, y, tw, tid);
}

// fft768(x,y): 4 passes, result in x.
__device__ __forceinline__ void fft768(float2* x, float2* y, const float2* tw, int tid) {
    fstage<3, 1,  256>(x, y, tw, tid);
    fstage<4, 3,  64 >(y, x, tw, tid);
    fstage<4, 12, 16 >(x, y, tw, tid);
    ffstage<4, 4, 48, 4>(y, x, tw, tid);     // (4,48,4)+(4,192,1)
}

// fft384(x,y): 4 passes, result in x.
__device__ __forceinline__ void fft384(float2* x, float2* y, const float2* tw, int tid) {
    fstage<3, 1,  128>(x, y, tw, tid);
    fstage<4, 3,  32 >(y, x, tw, tid);
    fstage<4, 12, 8  >(x, y, tw, tid);
    ffstage<4, 2, 48, 2>(y, x, tw, tid);     // (4,48,2)+(2,192,1)
}

// fft192(x,y): 3 passes, result in y.
__device__ __forceinline__ void fft192(float2* x, float2* y, const float2* tw, int tid) {
    fstage<3, 1, 64>(x, y, tw, tid);
    fstage<4, 3, 16>(y, x, tw, tid);
    ffstage<4, 4, 12, 4>(x, y, tw, tid);     // (4,12,4)+(4,48,1): 12 lanes, stride-1 stores
}

// Spectral 2:1 box downsample (exact alias identity).
__device__ __forceinline__ void derive_half(const float2* __restrict__ Z,
                                            float2* __restrict__ Zd,
                                            int M, int step, const float2* __restrict__ tw, int tid) {
    for (int k = tid; k < M; k += 256) {
        float2 a = Z[k], b = Z[k + M];
        float sr = a.x + b.x, si = a.y + b.y;
        float dr = a.x - b.x, di = a.y - b.y;
        float2 t = tw[k * step];
        float cdr = t.x * dr + t.y * di;       // conj(t) * d
        float cdi = t.x * di - t.y * dr;
        Zd[k] = make_float2(0.25f * (sr + cdr), 0.25f * (si + cdi));
    }
    __syncthreads();
}

// Whitened cross-spectrum IN-PLACE (Z len N -> R[0..N/2]).
__device__ __forceinline__ void herm_inplace(float2* A, int N, float f, int tid) {
    int half = N >> 1;
    float2 rv[4]; int ws[4]; int cnt = 0;
    for (int w = tid; w <= half; w += 256) {
        int iw = (w == 0) ? 0 : N - w;
        float2 Zw = A[w], Zm = A[iw];
        float Qx = 0.5f * (Zw.x + Zm.x), Qy = 0.5f * (Zw.y - Zm.y);
        float Kx = 0.5f * (Zw.y + Zm.y), Ky = -0.5f * (Zw.x - Zm.x);
        float kmag = sqrtf(Kx * Kx + Ky * Ky);
        float sc   = f * f / (f * kmag + 1e-8f);
        rv[cnt] = make_float2((Qx * Kx + Qy * Ky) * sc, (Qy * Kx - Qx * Ky) * sc);
        ws[cnt] = w; cnt++;
    }
    __syncthreads();
    for (int i = 0; i < cnt; i++) A[ws[i]] = rv[i];
    __syncthreads();
}

// Out-of-place whitened cross-spectrum.
__device__ __forceinline__ void herm_split(const float2* __restrict__ a,
                                           float2* __restrict__ b,
                                           int N, float f, int tid) {
    int half = N >> 1;
    for (int w = tid; w <= half; w += 256) {
        int iw = (w == 0) ? 0 : N - w;
        float2 Zw = a[w], Zm = a[iw];
        float Qx = 0.5f * (Zw.x + Zm.x), Qy = 0.5f * (Zw.y - Zm.y);
        float Kx = 0.5f * (Zw.y + Zm.y), Ky = -0.5f * (Zw.x - Zm.x);
        float kmag = sqrtf(Kx * Kx + Ky * Ky);
        float sc   = f * f / (f * kmag + 1e-8f);
        b[w] = make_float2((Qx * Kx + Qy * Ky) * sc, (Qy * Kx - Qx * Ky) * sc);
    }
    __syncthreads();
}

// Packed half-length inverse input IN-PLACE: R[0..M] -> z[0..M-1].
__device__ __forceinline__ void zbuild_inplace(float2* A, int M, int stepN,
                                               const float2* __restrict__ tw, int tid) {
    float2 zv[3]; int ms[3]; int cnt = 0;
    for (int m = tid; m < M; m += 256) {
        int im = M - m;
        float2 R0 = A[m];
        float2 C  = A[im];
        float Ci = (m ? -C.y : C.y);
        float Er = 0.5f * (R0.x + C.x), Ei = 0.5f * (R0.y + Ci);
        float Dr = 0.5f * (R0.x - C.x), Di = 0.5f * (R0.y - Ci);
        float2 t = tw[m * stepN];
        float wr = t.x, wi = -t.y;           // e^{+2*pi*i*m/N}
        float Or = Dr * wr - Di * wi;
        float Oi = Dr * wi + Di * wr;
        zv[cnt] = make_float2(Er - Oi, Ei + Or);
        ms[cnt] = m; cnt++;
    }
    __syncthreads();
    for (int i = 0; i < cnt; i++) A[ms[i]] = zv[i];
    __syncthreads();
}

// c[idx] from forward-FFT'd z (length M).
__device__ __forceinline__ float cval(const float2* zf, int M, int idx) {
    int p = idx >> 1;
    int q = p ? (M - p) : 0;
    float2 v = zf[q];
    return (idx & 1) ? v.y : v.x;
}

// ---------------- K2: per-(b,h,e) 3-scale whitened autocorrelation ----------------
// One forward FFT; Z2/Z4 derived spectrally; tail-fused inverse FFTs.
// smem: A (1536 f2) + B (1536 f2) + tw (1024 f2) = 32768 B.
__global__ __launch_bounds__(256) void k2_corr() {
    extern __shared__ float2 sm2[];
    float2* A  = sm2;             // 1536
    float2* B  = sm2 + 1536;      // 1536
    float2* tw = sm2 + 3072;      // 1024

    int tid = threadIdx.x;
    int bhe = blockIdx.x;
    int b = bhe >> 9;
    const float* qrow = g_qr + (size_t)bhe * LL;
    const float* krow = g_kr + (size_t)bhe * LL;

    const float TWO_PI_OVER = -6.283185307179586f / 1536.f;
    for (int t = tid; t < 1024; t += 256) {
        float s, c; __sincosf(TWO_PI_OVER * (float)t, &s, &c);
        tw[t] = make_float2(c, s);
    }
    for (int i = tid; i < LL; i += 256)
        A[i] = make_float2(qrow[i], krow[i]);
    float f = g_scal[0];
    float acc0, acc1, acc2, acc3, acc4, acc5;
    __syncthreads();

    // ---- forward FFT of packed signal: Z in B (A becomes scratch) ----
    fft1536(A, B, tw, tid);

    // ---- derive downsampled spectra into A ----
    derive_half(B, A, 768, 1, tw, tid);        // Z2 in A[0..767]
    derive_half(A, A + 768, 384, 2, tw, tid);  // Z4 in A[768..1151]

    // ======== scale 1 (N=1536, M=768) ========
    herm_inplace(B, 1536, f, tid);             // R[0..768] in B
    zbuild_inplace(B, 768, 1, tw, tid);        // z in B[0..767]
    fft768(B, B + 768, tw, tid);               // zf in B[0..767]
    {
        float wgt = g_scal[1] * (1.f / 768.f);
        acc0 = wgt * cval(B, 768, tid);
        acc1 = wgt * cval(B, 768, tid + 256);
        acc2 = wgt * cval(B, 768, tid + 512);
        acc3 = wgt * cval(B, 768, tid + 768);
        acc4 = wgt * cval(B, 768, tid + 1024);
        acc5 = wgt * cval(B, 768, tid + 1280);
    }
    __syncthreads();

    // ======== scale 2 (N=768, M=384) ========
    herm_split(A, B, 768, f, tid);             // R[0..384] in B
    zbuild_inplace(B, 384, 2, tw, tid);        // z in B[0..383]
    fft384(B, B + 384, tw, tid);               // zf in B[0..383]
    {
        float wgt = g_scal[2] * (1.f / 384.f);
        const int N = 768;
        #pragma unroll
        for (int i = 0; i < 6; i++) {
            int l = tid + 256 * i;
            float coords = ((float)l + 0.5f) * 0.5f - 0.5f;
            coords = fminf(fmaxf(coords, 0.f), (float)(N - 1));
            int lo = (int)floorf(coords);
            int hi = min(lo + 1, N - 1);
            float fr = coords - (float)lo;
            float add = wgt * (cval(B, 384, lo) * (1.f - fr) + cval(B, 384, hi) * fr);
            if (i == 0) acc0 += add; else if (i == 1) acc1 += add;
            else if (i == 2) acc2 += add; else if (i == 3) acc3 += add;
            else if (i == 4) acc4 += add; else acc5 += add;
        }
    }
    __syncthreads();

    // ======== scale 4 (N=384, M=192) ========
    herm_split(A + 768, B, 384, f, tid);       // R[0..192] in B
    zbuild_inplace(B, 192, 4, tw, tid);        // z in B[0..191]
    fft192(B, B + 192, tw, tid);               // zf in B[192..383]
    {
        float wgt = g_scal[3] * (1.f / 192.f);
        const float2* zf = B + 192;
        const int N = 384;
        #pragma unroll
        for (int i = 0; i < 6; i++) {
            int l = tid + 256 * i;
            float coords = ((float)l + 0.5f) * 0.25f - 0.5f;
            coords = fminf(fmaxf(coords, 0.f), (float)(N - 1));
            int lo = (int)floorf(coords);
            int hi = min(lo + 1, N - 1);
            float fr = coords - (float)lo;
            float add = wgt * (cval(zf, 192, lo) * (1.f - fr) + cval(zf, 192, hi) * fr);
            if (i == 0) acc0 += add; else if (i == 1) acc1 += add;
            else if (i == 2) acc2 += add; else if (i == 3) acc3 += add;
            else if (i == 4) acc4 += add; else acc5 += add;
        }
    }

    float* gm = g_mean + b * LL;
    atomicAdd(gm + tid,        fminf(fmaxf(acc0, -10.f), 10.f));
    atomicAdd(gm + tid + 256,  fminf(fmaxf(acc1, -10.f), 10.f));
    atomicAdd(gm + tid + 512,  fminf(fmaxf(acc2, -10.f), 10.f));
    atomicAdd(gm + tid + 768,  fminf(fmaxf(acc3, -10.f), 10.f));
    atomicAdd(gm + tid + 1024, fminf(fmaxf(acc4, -10.f), 10.f));
    atomicAdd(gm + tid + 1280, fminf(fmaxf(acc5, -10.f), 10.f));
}

// ---------------- K3: per-batch top-7 + softmax (4 warps) ----------------
__global__ __launch_bounds__(128) void k3_topk() {
    __shared__ float swv[4];
    __shared__ int   swi[4];
    __shared__ int   s_sel;
    __shared__ float s_wk[TOPK];
    int b = blockIdx.x;
    int tid = threadIdx.x;
    int lane = tid & 31, w = tid >> 5;
    float v[12];
    #pragma unroll
    for (int i = 0; i < 12; i++)
        v[i] = g_mean[b * LL + tid + 128 * i] * (1.f / HE);

    int dk[TOPK];
    for (int it = 0; it < TOPK; it++) {
        float best = -3.0e38f; int bi = 0;
        #pragma unroll
        for (int i = 0; i < 12; i++)
            if (v[i] > best) { best = v[i]; bi = tid + 128 * i; }
        #pragma unroll
        for (int off = 16; off; off >>= 1) {
            float ov = __shfl_down_sync(0xffffffffu, best, off);
            int   oi = __shfl_down_sync(0xffffffffu, bi,   off);
            if (ov > best || (ov == best && oi < bi)) { best = ov; bi = oi; }
        }
        if (lane == 0) { swv[w] = best; swi[w] = bi; }
        __syncthreads();
        if (tid == 0) {
            float bb = swv[0]; int bj = swi[0];
            #pragma unroll
            for (int qq = 1; qq < 4; qq++)
                if (swv[qq] > bb || (swv[qq] == bb && swi[qq] < bj)) { bb = swv[qq]; bj = swi[qq]; }
            s_wk[it] = bb; s_sel = bj;
        }
        __syncthreads();
        int sel = s_sel;
        dk[it] = sel;
        if ((sel & 127) == tid) v[sel >> 7] = -3.0e38f;
    }
    if (tid == 0) {
        float mx = s_wk[0];
        #pragma unroll
        for (int i = 1; i < TOPK; i++) mx = fmaxf(mx, s_wk[i]);
        float e[TOPK], ssum = 0.f;
        #pragma unroll
        for (int i = 0; i < TOPK; i++) { e[i] = expf(s_wk[i] - mx); ssum += e[i]; }
        #pragma unroll
        for (int i = 0; i < TOPK; i++) {
            g_nw[b * TOPK + i] = e[i] / ssum;
            g_delays[b * TOPK + i] = dk[i];
        }
    }
}

// ---------------- K4: delayed-values aggregation ----------------
__global__ __launch_bounds__(128) void k4_out(const float* __restrict__ vals,
                                              float* __restrict__ out) {
    __shared__ float s_nw[TOPK];
    __shared__ int   s_dl[TOPK];
    int bl = blockIdx.x;
    int b = bl / LL;
    int l = bl - b * LL;
    int tid = threadIdx.x;
    if (tid < TOPK) {
        s_nw[tid] = g_nw[b * TOPK + tid];
        s_dl[tid] = g_delays[b * TOPK + tid];
    }
    __syncthreads();
    float4 acc = make_float4(0.f, 0.f, 0.f, 0.f);
    #pragma unroll
    for (int k = 0; k < TOPK; k++) {
        int ls = l + s_dl[k]; if (ls >= LL) ls -= LL;
        float nwk = s_nw[k];
        const float4* src = (const float4*)(vals + ((size_t)b * LL + ls) * HE);
        float4 v = src[tid];
        acc.x += nwk * v.x; acc.y += nwk * v.y;
        acc.z += nwk * v.z; acc.w += nwk * v.w;
    }
    ((float4*)(out + ((size_t)b * LL + l) * HE))[tid] = acc;
}

// ---------------- launch ----------------
extern "C" void kernel_launch(void* const* d_in, const int* in_sizes, int n_in,
                              void* d_out, int out_size) {
    const float* q  = (const float*)d_in[0];
    const float* kk = (const float*)d_in[1];
    const float* v  = (const float*)d_in[2];
    const float* sw = (const float*)d_in[3];
    const float* ff = (const float*)d_in[4];

    const int K2_SMEM = 32768;  // (1536*2 + 1024) float2 = 4096*8 B

    dim3 g1(48, 64, 2);
    k1_ln<<<g1, 256>>>(q, kk, sw, ff);
    k2_corr<<<BHE, 256, K2_SMEM>>>();
    k3_topk<<<BB, 128>>>();
    k4_out<<<BB * LL, 128>>>(v, (float*)d_out);
}

// round 13
// speedup vs baseline: 1.0312x; 1.0312x over previous
#include <cuda_runtime.h>
#include <math.h>

#define BB 8
#define LL 1536
#define HH 8
#define EE 64
#define HE 512          // H*E
#define BHE 4096        // B*H*E
#define TOPK 7          // int(log(1536)) = 7

// ---------------- scratch (static __device__, no allocation) ----------------
__device__ float g_qr[(size_t)BHE * LL];   // layernormed q, (b,h,e,l)
__device__ float g_kr[(size_t)BHE * LL];   // layernormed k, (b,h,e,l)
__device__ float g_mean[BB * LL];          // sum over (h,e) of clipped corr
__device__ float g_scal[4];                // [0]=sigmoid(freq), [1..3]=softmax(scale_weights)
__device__ int   g_delays[BB * TOPK];
__device__ float g_nw[BB * TOPK];
__device__ int   g_ctr[BB];                // per-batch completion counters

// ---------------- K1: LayerNorm over E + transpose; block(0,0,0) also inits ----
__global__ __launch_bounds__(256) void k1_ln(const float* __restrict__ q,
                                             const float* __restrict__ kk,
                                             const float* __restrict__ sw,
                                             const float* __restrict__ ff) {
    __shared__ float tile[32][EE + 1];
    __shared__ float mu[32], isd[32];
    int tid = threadIdx.x;
    if (blockIdx.x == 0 && blockIdx.y == 0 && blockIdx.z == 0) {
        for (int i = tid; i < BB * LL; i += 256) g_mean[i] = 0.f;
        if (tid < BB) g_ctr[tid] = 0;
        if (tid == 0) {
            g_scal[0] = 1.f / (1.f + expf(-ff[0]));
            float a = sw[0], b = sw[1], c = sw[2];
            float mx = fmaxf(a, fmaxf(b, c));
            float ea = expf(a - mx), eb = expf(b - mx), ec = expf(c - mx);
            float s = ea + eb + ec;
            g_scal[1] = ea / s; g_scal[2] = eb / s; g_scal[3] = ec / s;
        }
    }
    int l0 = blockIdx.x * 32;
    int bh = blockIdx.y;                 // b*8 + h
    int b  = bh >> 3, h = bh & 7;
    const float* in = blockIdx.z ? kk : q;
    float* out      = blockIdx.z ? g_kr : g_qr;
    int e = tid & 63, r0 = tid >> 6;
    for (int r = r0; r < 32; r += 4)
        tile[r][e] = in[(((size_t)b * LL + l0 + r) * HH + h) * EE + e];
    __syncthreads();
    int lane = tid & 31, w = tid >> 5;
    for (int r = w; r < 32; r += 8) {
        float x0 = tile[r][lane], x1 = tile[r][lane + 32];
        float s = x0 + x1, s2 = x0 * x0 + x1 * x1;
        #pragma unroll
        for (int off = 16; off; off >>= 1) {
            s  += __shfl_down_sync(0xffffffffu, s,  off);
            s2 += __shfl_down_sync(0xffffffffu, s2, off);
        }
        if (lane == 0) {
            float m = s * (1.f / EE);
            float v = s2 * (1.f / EE) - m * m;
            mu[r] = m; isd[r] = rsqrtf(v + 1e-5f);
        }
    }
    __syncthreads();
    int li = tid & 31, e0 = tid >> 5;
    for (int ee = e0; ee < EE; ee += 8) {
        float val = (tile[li][ee] - mu[li]) * isd[li];
        out[(((size_t)bh) * EE + ee) * LL + l0 + li] = val;
    }
}

// ---------------- FFT: templated Stockham (R11 structure), AoS float2 ----------
// tw[t] = exp(-2*pi*i*t/1536), t in [0,1024).

template<int R, int M, int L>
__device__ __forceinline__ void fstage(const float2* __restrict__ a,
                                       float2* __restrict__ b,
                                       const float2* __restrict__ tw, int tid) {
    constexpr int NB   = L * M;            // butterflies; also the input stride
    constexpr int STEP = 1536 / (R * L);
    for (int t = tid; t < NB; t += 256) {
        int j = t / M;                     // compile-time M -> mul/shift
        int k = t - j * M;
        int wb = k + (M * R) * j;
        float2 w1 = tw[j * STEP];
        if (R == 4) {
            float2 w2 = tw[2 * j * STEP];
            float w3r = w1.x * w2.x - w1.y * w2.y;
            float w3i = w1.x * w2.y + w1.y * w2.x;
            float2 c0 = a[t], c1 = a[t + NB], c2 = a[t + 2 * NB], c3 = a[t + 3 * NB];
            float t0r = c0.x + c2.x, t0i = c0.y + c2.y;
            float t1r = c0.x - c2.x, t1i = c0.y - c2.y;
            float t2r = c1.x + c3.x, t2i = c1.y + c3.y;
            float t3r = c1.x - c3.x, t3i = c1.y - c3.y;
            float d0r = t0r + t2r, d0i = t0i + t2i;
            float d2r = t0r - t2r, d2i = t0i - t2i;
            float d1r = t1r + t3i, d1i = t1i - t3r;   // t1 - i*t3
            float d3r = t1r - t3i, d3i = t1i + t3r;   // t1 + i*t3
            b[wb]         = make_float2(d0r, d0i);
            b[wb + M]     = make_float2(d1r * w1.x - d1i * w1.y, d1r * w1.y + d1i * w1.x);
            b[wb + 2 * M] = make_float2(d2r * w2.x - d2i * w2.y, d2r * w2.y + d2i * w2.x);
            b[wb + 3 * M] = make_float2(d3r * w3r - d3i * w3i, d3r * w3i + d3i * w3r);
        } else if (R == 3) {
            float2 w2 = tw[2 * j * STEP];
            float2 c0 = a[t], c1 = a[t + NB], c2 = a[t + 2 * NB];
            float t1r = c1.x + c2.x, t1i = c1.y + c2.y;
            float ur  = c0.x - 0.5f * t1r, ui = c0.y - 0.5f * t1i;
            const float s3 = 0.8660254037844386f;
            float vr = s3 * (c1.x - c2.x), vi = s3 * (c1.y - c2.y);
            float d0r = c0.x + t1r, d0i = c0.y + t1i;
            float d1r = ur + vi, d1i = ui - vr;        // u - i*v
            float d2r = ur - vi, d2i = ui + vr;        // u + i*v
            b[wb]         = make_float2(d0r, d0i);
            b[wb + M]     = make_float2(d1r * w1.x - d1i * w1.y, d1r * w1.y + d1i * w1.x);
            b[wb + 2 * M] = make_float2(d2r * w2.x - d2i * w2.y, d2r * w2.y + d2i * w2.x);
        } else {  // R == 2
            float2 c0 = a[t], c1 = a[t + NB];
            float d1r = c0.x - c1.x, d1i = c0.y - c1.y;
            b[wb]     = make_float2(c0.x + c1.x, c0.y + c1.y);
            b[wb + M] = make_float2(d1r * w1.x - d1i * w1.y, d1r * w1.y + d1i * w1.x);
        }
    }
    __syncthreads();
}

// fft1536(A,B): 6 stages, result in A.
__device__ __forceinline__ void fft1536(float2* x, float2* y, const float2* tw, int tid) {
    fstage<3, 1,   512>(x, y, tw, tid);
    fstage<4, 3,   128>(y, x, tw, tid);
    fstage<4, 12,  32 >(x, y, tw, tid);
    fstage<4, 48,  8  >(y, x, tw, tid);
    fstage<4, 192, 2  >(x, y, tw, tid);
    fstage<2, 768, 1  >(y, x, tw, tid);
}

// fft768(x,y): 5 stages, result in y.
__device__ __forceinline__ void fft768(float2* x, float2* y, const float2* tw, int tid) {
    fstage<3, 1,   256>(x, y, tw, tid);
    fstage<4, 3,   64 >(y, x, tw, tid);
    fstage<4, 12,  16 >(x, y, tw, tid);
    fstage<4, 48,  4  >(y, x, tw, tid);
    fstage<4, 192, 1  >(x, y, tw, tid);
}

// fft384(x,y): 5 stages, result in y.
__device__ __forceinline__ void fft384(float2* x, float2* y, const float2* tw, int tid) {
    fstage<3, 1,   128>(x, y, tw, tid);
    fstage<4, 3,   32 >(y, x, tw, tid);
    fstage<4, 12,  8  >(x, y, tw, tid);
    fstage<4, 48,  2  >(y, x, tw, tid);
    fstage<2, 192, 1  >(x, y, tw, tid);
}

// fft192(x,y): 4 stages, result in x.
__device__ __forceinline__ void fft192(float2* x, float2* y, const float2* tw, int tid) {
    fstage<3, 1,   64 >(x, y, tw, tid);
    fstage<4, 3,   16 >(y, x, tw, tid);
    fstage<4, 12,  4  >(x, y, tw, tid);
    fstage<4, 48,  1  >(y, x, tw, tid);
}

// Spectral 2:1 box downsample: Zd[k] = 1/4 [ (Z[k]+Z[k+M]) + conj(tw[k*step])*(Z[k]-Z[k+M]) ]
__device__ __forceinline__ void derive_half(const float2* __restrict__ Z,
                                            float2* __restrict__ Zd,
                                            int M, int step, const float2* __restrict__ tw, int tid) {
    for (int k = tid; k < M; k += 256) {
        float2 a = Z[k], b = Z[k + M];
        float sr = a.x + b.x, si = a.y + b.y;
        float dr = a.x - b.x, di = a.y - b.y;
        float2 t = tw[k * step];
        float cdr = t.x * dr + t.y * di;       // conj(t) * d
        float cdi = t.x * di - t.y * dr;
        Zd[k] = make_float2(0.25f * (sr + cdr), 0.25f * (si + cdi));
    }
    __syncthreads();
}

// Whitened cross-spectrum, IN-PLACE on A (Z len N -> R[0..N/2]).
__device__ __forceinline__ void herm_inplace(float2* A, int N, float f, int tid) {
    int half = N >> 1;
    float2 rv[4]; int ws[4]; int cnt = 0;
    for (int w = tid; w <= half; w += 256) {
        int iw = (w == 0) ? 0 : N - w;
        float2 Zw = A[w], Zm = A[iw];
        float Qx = 0.5f * (Zw.x + Zm.x), Qy = 0.5f * (Zw.y - Zm.y);
        float Kx = 0.5f * (Zw.y + Zm.y), Ky = -0.5f * (Zw.x - Zm.x);
        float kmag = sqrtf(Kx * Kx + Ky * Ky);
        float sc   = f * f / (f * kmag + 1e-8f);
        rv[cnt] = make_float2((Qx * Kx + Qy * Ky) * sc, (Qy * Kx - Qx * Ky) * sc);
        ws[cnt] = w; cnt++;
    }
    __syncthreads();
    for (int i = 0; i < cnt; i++) A[ws[i]] = rv[i];
    __syncthreads();
}

// Out-of-place whitened cross-spectrum.
__device__ __forceinline__ void herm_split(const float2* __restrict__ a,
                                           float2* __restrict__ b,
                                           int N, float f, int tid) {
    int half = N >> 1;
    for (int w = tid; w <= half; w += 256) {
        int iw = (w == 0) ? 0 : N - w;
        float2 Zw = a[w], Zm = a[iw];
        float Qx = 0.5f * (Zw.x + Zm.x), Qy = 0.5f * (Zw.y - Zm.y);
        float Kx = 0.5f * (Zw.y + Zm.y), Ky = -0.5f * (Zw.x - Zm.x);
        float kmag = sqrtf(Kx * Kx + Ky * Ky);
        float sc   = f * f / (f * kmag + 1e-8f);
        b[w] = make_float2((Qx * Kx + Qy * Ky) * sc, (Qy * Kx - Qx * Ky) * sc);
    }
    __syncthreads();
}

// Packed half-length inverse input, IN-PLACE: R[0..M] -> z[0..M-1].
__device__ __forceinline__ void zbuild_inplace(float2* A, int M, int stepN,
                                               const float2* __restrict__ tw, int tid) {
    float2 zv[3]; int ms[3]; int cnt = 0;
    for (int m = tid; m < M; m += 256) {
        int im = M - m;                      // m=0 -> M
        float2 R0 = A[m];
        float2 C  = A[im];
        float Ci = (m ? -C.y : C.y);
        float Er = 0.5f * (R0.x + C.x), Ei = 0.5f * (R0.y + Ci);
        float Dr = 0.5f * (R0.x - C.x), Di = 0.5f * (R0.y - Ci);
        float2 t = tw[m * stepN];
        float wr = t.x, wi = -t.y;           // e^{+2*pi*i*m/N}
        float Or = Dr * wr - Di * wi;
        float Oi = Dr * wi + Di * wr;
        zv[cnt] = make_float2(Er - Oi, Ei + Or);
        ms[cnt] = m; cnt++;
    }
    __syncthreads();
    for (int i = 0; i < cnt; i++) A[ms[i]] = zv[i];
    __syncthreads();
}

// c[idx] from forward-FFT'd z (length M).
__device__ __forceinline__ float cval(const float2* zf, int M, int idx) {
    int p = idx >> 1;
    int q = p ? (M - p) : 0;
    float2 v = zf[q];
    return (idx & 1) ? v.y : v.x;
}

// ---------------- K2: 3-scale whitened autocorrelation + fused last-CTA topk ----
// smem: A (1536 f2) + B (1536 f2) + tw (1024 f2) = 32768 B.
__global__ __launch_bounds__(256, 5) void k2_corr() {
    extern __shared__ float2 sm2[];
    float2* A  = sm2;             // 1536
    float2* B  = sm2 + 1536;      // 1536 (Z2 at [0..767], Z4 at [768..1151])
    float2* tw = sm2 + 3072;      // 1024

    int tid = threadIdx.x;
    int bhe = blockIdx.x;
    int b = bhe >> 9;
    const float* qrow = g_qr + (size_t)bhe * LL;
    const float* krow = g_kr + (size_t)bhe * LL;

    const float TWO_PI_OVER = -6.283185307179586f / 1536.f;
    for (int t = tid; t < 1024; t += 256) {
        float s, c; __sincosf(TWO_PI_OVER * (float)t, &s, &c);
        tw[t] = make_float2(c, s);
    }
    for (int i = tid; i < LL; i += 256)
        A[i] = make_float2(qrow[i], krow[i]);
    float f = g_scal[0];
    float acc0, acc1, acc2, acc3, acc4, acc5;
    __syncthreads();

    // ---- one forward FFT of the packed signal ----
    fft1536(A, B, tw, tid);                  // Z in A

    // ---- derive downsampled spectra (exact alias identities) ----
    derive_half(A, B, 768, 1, tw, tid);      // Z2 in B[0..767]
    derive_half(B, B + 768, 384, 2, tw, tid);// Z4 in B[768..1151]

    // ======== scale 1 (N=1536, M=768) ========
    herm_inplace(A, 1536, f, tid);           // R[0..768] in A
    zbuild_inplace(A, 768, 1, tw, tid);      // z in A[0..767]
    fft768(A, A + 768, tw, tid);             // zf in A[768..1535]
    {
        float wgt = g_scal[1] * (1.f / 768.f);
        const float2* zf = A + 768;
        acc0 = wgt * cval(zf, 768, tid);
        acc1 = wgt * cval(zf, 768, tid + 256);
        acc2 = wgt * cval(zf, 768, tid + 512);
        acc3 = wgt * cval(zf, 768, tid + 768);
        acc4 = wgt * cval(zf, 768, tid + 1024);
        acc5 = wgt * cval(zf, 768, tid + 1280);
    }
    __syncthreads();

    // ======== scale 2 (N=768, M=384) ========
    herm_split(B, A, 768, f, tid);           // R[0..384] in A
    zbuild_inplace(A, 384, 2, tw, tid);      // z in A[0..383]
    fft384(A, A + 384, tw, tid);             // zf in A[384..767]
    {
        float wgt = g_scal[2] * (1.f / 384.f);
        const float2* zf = A + 384;
        const int N = 768;
        #pragma unroll
        for (int i = 0; i < 6; i++) {
            int l = tid + 256 * i;
            float coords = ((float)l + 0.5f) * 0.5f - 0.5f;
            coords = fminf(fmaxf(coords, 0.f), (float)(N - 1));
            int lo = (int)floorf(coords);
            int hi = min(lo + 1, N - 1);
            float fr = coords - (float)lo;
            float add = wgt * (cval(zf, 384, lo) * (1.f - fr) + cval(zf, 384, hi) * fr);
            if (i == 0) acc0 += add; else if (i == 1) acc1 += add;
            else if (i == 2) acc2 += add; else if (i == 3) acc3 += add;
            else if (i == 4) acc4 += add; else acc5 += add;
        }
    }
    __syncthreads();

    // ======== scale 4 (N=384, M=192) ========
    herm_split(B + 768, A, 384, f, tid);     // R[0..192] in A
    zbuild_inplace(A, 192, 4, tw, tid);      // z in A[0..191]
    fft192(A, A + 192, tw, tid);             // zf in A[0..191]
    {
        float wgt = g_scal[3] * (1.f / 192.f);
        const int N = 384;
        #pragma unroll
        for (int i = 0; i < 6; i++) {
            int l = tid + 256 * i;
            float coords = ((float)l + 0.5f) * 0.25f - 0.5f;
            coords = fminf(fmaxf(coords, 0.f), (float)(N - 1));
            int lo = (int)floorf(coords);
            int hi = min(lo + 1, N - 1);
            float fr = coords - (float)lo;
            float add = wgt * (cval(A, 192, lo) * (1.f - fr) + cval(A, 192, hi) * fr);
            if (i == 0) acc0 += add; else if (i == 1) acc1 += add;
            else if (i == 2) acc2 += add; else if (i == 3) acc3 += add;
            else if (i == 4) acc4 += add; else acc5 += add;
        }
    }

    float* gm = g_mean + b * LL;
    atomicAdd(gm + tid,        fminf(fmaxf(acc0, -10.f), 10.f));
    atomicAdd(gm + tid + 256,  fminf(fmaxf(acc1, -10.f), 10.f));
    atomicAdd(gm + tid + 512,  fminf(fmaxf(acc2, -10.f), 10.f));
    atomicAdd(gm + tid + 768,  fminf(fmaxf(acc3, -10.f), 10.f));
    atomicAdd(gm + tid + 1024, fminf(fmaxf(acc4, -10.f), 10.f));
    atomicAdd(gm + tid + 1280, fminf(fmaxf(acc5, -10.f), 10.f));

    // ---- last CTA of this batch performs top-7 + softmax (threadFenceReduction) ----
    __threadfence();
    __syncthreads();
    __shared__ int s_last;
    if (tid == 0) {
        int ticket = atomicAdd(&g_ctr[b], 1);
        s_last = (ticket == (BHE / BB) - 1);
    }
    __syncthreads();
    if (!s_last) return;
    __threadfence();

    {
        __shared__ float swv[8];
        __shared__ int   swi[8];
        __shared__ int   s_sel;
        __shared__ float s_wk[TOPK];
        __shared__ int   s_dk[TOPK];
        int lane = tid & 31, w = tid >> 5;
        float v[6];
        #pragma unroll
        for (int i = 0; i < 6; i++)
            v[i] = g_mean[b * LL + tid + 256 * i] * (1.f / HE);

        for (int it = 0; it < TOPK; it++) {
            float best = -3.0e38f; int bi = 0;
            #pragma unroll
            for (int i = 0; i < 6; i++)
                if (v[i] > best) { best = v[i]; bi = tid + 256 * i; }
            #pragma unroll
            for (int off = 16; off; off >>= 1) {
                float ov = __shfl_down_sync(0xffffffffu, best, off);
                int   oi = __shfl_down_sync(0xffffffffu, bi,   off);
                if (ov > best || (ov == best && oi < bi)) { best = ov; bi = oi; }
            }
            if (lane == 0) { swv[w] = best; swi[w] = bi; }
            __syncthreads();
            if (tid == 0) {
                float bb = swv[0]; int bj = swi[0];
                #pragma unroll
                for (int qq = 1; qq < 8; qq++)
                    if (swv[qq] > bb || (swv[qq] == bb && swi[qq] < bj)) { bb = swv[qq]; bj = swi[qq]; }
                s_wk[it] = bb; s_dk[it] = bj; s_sel = bj;
            }
            __syncthreads();
            int sel = s_sel;
            if ((sel & 255) == tid) v[sel >> 8] = -3.0e38f;
        }
        if (tid == 0) {
            float mx = s_wk[0];
            #pragma unroll
            for (int i = 1; i < TOPK; i++) mx = fmaxf(mx, s_wk[i]);
            float e[TOPK], ssum = 0.f;
            #pragma unroll
            for (int i = 0; i < TOPK; i++) { e[i] = expf(s_wk[i] - mx); ssum += e[i]; }
            #pragma unroll
            for (int i = 0; i < TOPK; i++) {
                g_nw[b * TOPK + i] = e[i] / ssum;
                g_delays[b * TOPK + i] = s_dk[i];
            }
        }
    }
}

// ---------------- K4: delayed-values aggregation (R11 version) ----------------
__global__ __launch_bounds__(128) void k4_out(const float* __restrict__ vals,
                                              float* __restrict__ out) {
    int bl = blockIdx.x;
    int b = bl / LL;
    int l = bl - b * LL;
    int tid = threadIdx.x;
    float nw[TOPK]; int dl[TOPK];
    #pragma unroll
    for (int k = 0; k < TOPK; k++) {
        nw[k] = g_nw[b * TOPK + k];
        dl[k] = g_delays[b * TOPK + k];
    }
    float4 acc = make_float4(0.f, 0.f, 0.f, 0.f);
    #pragma unroll
    for (int k = 0; k < TOPK; k++) {
        int ls = l + dl[k]; if (ls >= LL) ls -= LL;
        const float4* src = (const float4*)(vals + ((size_t)b * LL + ls) * HE);
        float4 v = src[tid];
        acc.x += nw[k] * v.x; acc.y += nw[k] * v.y;
        acc.z += nw[k] * v.z; acc.w += nw[k] * v.w;
    }
    ((float4*)(out + ((size_t)b * LL + l) * HE))[tid] = acc;
}

// ---------------- launch ----------------
extern "C" void kernel_launch(void* const* d_in, const int* in_sizes, int n_in,
                              void* d_out, int out_size) {
    const float* q  = (const float*)d_in[0];
    const float* kk = (const float*)d_in[1];
    const float* v  = (const float*)d_in[2];
    const float* sw = (const float*)d_in[3];
    const float* ff = (const float*)d_in[4];

    const int K2_SMEM = 32768;  // (1536*2 + 1024) float2 = 4096*8 B

    dim3 g1(48, 64, 2);
    k1_ln<<<g1, 256>>>(q, kk, sw, ff);
    k2_corr<<<BHE, 256, K2_SMEM>>>();
    k4_out<<<BB * LL, 128>>>(v, (float*)d_out);
}

// round 14
// speedup vs baseline: 1.1484x; 1.1136x over previous
#include <cuda_runtime.h>
#include <math.h>

#define BB 8
#define LL 1536
#define HH 8
#define EE 64
#define HE 512          // H*E
#define BHE 4096        // B*H*E
#define TOPK 7          // int(log(1536)) = 7

// ---------------- scratch (static __device__, no allocation) ----------------
__device__ float g_qr[(size_t)BHE * LL];   // layernormed q, (b,h,e,l)
__device__ float g_kr[(size_t)BHE * LL];   // layernormed k, (b,h,e,l)
__device__ float g_mean[BB * LL];          // sum over (h,e) of clipped corr
__device__ float g_scal[4];                // [0]=sigmoid(freq), [1..3]=softmax(scale_weights)
__device__ int   g_delays[BB * TOPK];
__device__ float g_nw[BB * TOPK];

// ---------------- K1: LayerNorm over E + transpose, 64x64 tile, q+k fused ----
// grid (24, 64): blockIdx.x = l-tile, blockIdx.y = bh. block 256.
__global__ __launch_bounds__(256) void k1_ln(const float* __restrict__ q,
                                             const float* __restrict__ kk,
                                             const float* __restrict__ sw,
                                             const float* __restrict__ ff) {
    __shared__ float tq[64 * 65];
    __shared__ float tk[64 * 65];
    __shared__ float muq[64], isq[64], muk[64], isk[64];
    int tid = threadIdx.x;
    if (blockIdx.x == 0 && blockIdx.y == 0) {
        for (int i = tid; i < BB * LL; i += 256) g_mean[i] = 0.f;
        if (tid == 0) {
            g_scal[0] = 1.f / (1.f + expf(-ff[0]));
            float a = sw[0], b = sw[1], c = sw[2];
            float mx = fmaxf(a, fmaxf(b, c));
            float ea = expf(a - mx), eb = expf(b - mx), ec = expf(c - mx);
            float s = ea + eb + ec;
            g_scal[1] = ea / s; g_scal[2] = eb / s; g_scal[3] = ec / s;
        }
    }
    int l0 = blockIdx.x * 64;
    int bh = blockIdx.y;                 // b*8 + h
    int b  = bh >> 3, h = bh & 7;

    // ---- load 64 rows x 64 e of q and k via float4 ----
    for (int idx = tid; idx < 1024; idx += 256) {
        int row = idx >> 4, c4 = idx & 15;
        size_t base = (((size_t)b * LL + l0 + row) * HH + h) * EE + c4 * 4;
        float4 vq = *(const float4*)(q + base);
        float4 vk = *(const float4*)(kk + base);
        int o = row * 65 + c4 * 4;
        tq[o] = vq.x; tq[o + 1] = vq.y; tq[o + 2] = vq.z; tq[o + 3] = vq.w;
        tk[o] = vk.x; tk[o + 1] = vk.y; tk[o + 2] = vk.z; tk[o + 3] = vk.w;
    }
    __syncthreads();

    // ---- reduce: warps 0-3 -> q rows, warps 4-7 -> k rows (16 rows each) ----
    {
        int lane = tid & 31, w = tid >> 5;
        const float* t = (w < 4) ? tq : tk;
        float* mu = (w < 4) ? muq : muk;
        float* is = (w < 4) ? isq : isk;
        int r0 = (w & 3) * 16;
        for (int r = r0; r < r0 + 16; r++) {
            float x0 = t[r * 65 + lane], x1 = t[r * 65 + lane + 32];
            float s = x0 + x1, s2 = x0 * x0 + x1 * x1;
            #pragma unroll
            for (int off = 16; off; off >>= 1) {
                s  += __shfl_down_sync(0xffffffffu, s,  off);
                s2 += __shfl_down_sync(0xffffffffu, s2, off);
            }
            if (lane == 0) {
                float m = s * (1.f / EE);
                float v = s2 * (1.f / EE) - m * m;
                mu[r] = m; is[r] = rsqrtf(v + 1e-5f);
            }
        }
    }
    __syncthreads();

    // ---- normalize + transposed write (float2 over l) ----
    {
        int li = tid & 31, eg = tid >> 5;
        int r0 = 2 * li, r1 = r0 + 1;
        float mq0 = muq[r0], iq0 = isq[r0], mq1 = muq[r1], iq1 = isq[r1];
        float mk0 = muk[r0], ik0 = isk[r0], mk1 = muk[r1], ik1 = isk[r1];
        #pragma unroll
        for (int i = 0; i < 8; i++) {
            int ee = eg + 8 * i;
            size_t off = ((size_t)bh * EE + ee) * LL + l0 + r0;
            float2 oq = make_float2((tq[r0 * 65 + ee] - mq0) * iq0,
                                    (tq[r1 * 65 + ee] - mq1) * iq1);
            float2 ok = make_float2((tk[r0 * 65 + ee] - mk0) * ik0,
                                    (tk[r1 * 65 + ee] - mk1) * ik1);
            *(float2*)(g_qr + off) = oq;
            *(float2*)(g_kr + off) = ok;
        }
    }
}

// ---------------- FFT: templated Stockham (R11 structure), AoS float2 ----------
// tw[t] = exp(-2*pi*i*t/1536), t in [0,1024).

template<int R, int M, int L>
__device__ __forceinline__ void fstage(const float2* __restrict__ a,
                                       float2* __restrict__ b,
                                       const float2* __restrict__ tw, int tid) {
    constexpr int NB   = L * M;            // butterflies; also the input stride
    constexpr int STEP = 1536 / (R * L);
    for (int t = tid; t < NB; t += 256) {
        int j = t / M;                     // compile-time M -> mul/shift
        int k = t - j * M;
        int wb = k + (M * R) * j;
        float2 w1 = tw[j * STEP];
        if (R == 4) {
            float2 w2 = tw[2 * j * STEP];
            float w3r = w1.x * w2.x - w1.y * w2.y;
            float w3i = w1.x * w2.y + w1.y * w2.x;
            float2 c0 = a[t], c1 = a[t + NB], c2 = a[t + 2 * NB], c3 = a[t + 3 * NB];
            float t0r = c0.x + c2.x, t0i = c0.y + c2.y;
            float t1r = c0.x - c2.x, t1i = c0.y - c2.y;
            float t2r = c1.x + c3.x, t2i = c1.y + c3.y;
            float t3r = c1.x - c3.x, t3i = c1.y - c3.y;
            float d0r = t0r + t2r, d0i = t0i + t2i;
            float d2r = t0r - t2r, d2i = t0i - t2i;
            float d1r = t1r + t3i, d1i = t1i - t3r;   // t1 - i*t3
            float d3r = t1r - t3i, d3i = t1i + t3r;   // t1 + i*t3
            b[wb]         = make_float2(d0r, d0i);
            b[wb + M]     = make_float2(d1r * w1.x - d1i * w1.y, d1r * w1.y + d1i * w1.x);
            b[wb + 2 * M] = make_float2(d2r * w2.x - d2i * w2.y, d2r * w2.y + d2i * w2.x);
            b[wb + 3 * M] = make_float2(d3r * w3r - d3i * w3i, d3r * w3i + d3i * w3r);
        } else if (R == 3) {
            float2 w2 = tw[2 * j * STEP];
            float2 c0 = a[t], c1 = a[t + NB], c2 = a[t + 2 * NB];
            float t1r = c1.x + c2.x, t1i = c1.y + c2.y;
            float ur  = c0.x - 0.5f * t1r, ui = c0.y - 0.5f * t1i;
            const float s3 = 0.8660254037844386f;
            float vr = s3 * (c1.x - c2.x), vi = s3 * (c1.y - c2.y);
            float d0r = c0.x + t1r, d0i = c0.y + t1i;
            float d1r = ur + vi, d1i = ui - vr;        // u - i*v
            float d2r = ur - vi, d2i = ui + vr;        // u + i*v
            b[wb]         = make_float2(d0r, d0i);
            b[wb + M]     = make_float2(d1r * w1.x - d1i * w1.y, d1r * w1.y + d1i * w1.x);
            b[wb + 2 * M] = make_float2(d2r * w2.x - d2i * w2.y, d2r * w2.y + d2i * w2.x);
        } else {  // R == 2
            float2 c0 = a[t], c1 = a[t + NB];
            float d1r = c0.x - c1.x, d1i = c0.y - c1.y;
            b[wb]     = make_float2(c0.x + c1.x, c0.y + c1.y);
            b[wb + M] = make_float2(d1r * w1.x - d1i * w1.y, d1r * w1.y + d1i * w1.x);
        }
    }
    __syncthreads();
}

// fft1536(A,B): 6 stages, result in A.
__device__ __forceinline__ void fft1536(float2* x, float2* y, const float2* tw, int tid) {
    fstage<3, 1,   512>(x, y, tw, tid);
    fstage<4, 3,   128>(y, x, tw, tid);
    fstage<4, 12,  32 >(x, y, tw, tid);
    fstage<4, 48,  8  >(y, x, tw, tid);
    fstage<4, 192, 2  >(x, y, tw, tid);
    fstage<2, 768, 1  >(y, x, tw, tid);
}

// fft768(x,y): 5 stages, result in y.
__device__ __forceinline__ void fft768(float2* x, float2* y, const float2* tw, int tid) {
    fstage<3, 1,   256>(x, y, tw, tid);
    fstage<4, 3,   64 >(y, x, tw, tid);
    fstage<4, 12,  16 >(x, y, tw, tid);
    fstage<4, 48,  4  >(y, x, tw, tid);
    fstage<4, 192, 1  >(x, y, tw, tid);
}

// fft384(x,y): 5 stages, result in y.
__device__ __forceinline__ void fft384(float2* x, float2* y, const float2* tw, int tid) {
    fstage<3, 1,   128>(x, y, tw, tid);
    fstage<4, 3,   32 >(y, x, tw, tid);
    fstage<4, 12,  8  >(x, y, tw, tid);
    fstage<4, 48,  2  >(y, x, tw, tid);
    fstage<2, 192, 1  >(x, y, tw, tid);
}

// fft192(x,y): 4 stages, result in x.
__device__ __forceinline__ void fft192(float2* x, float2* y, const float2* tw, int tid) {
    fstage<3, 1,   64 >(x, y, tw, tid);
    fstage<4, 3,   16 >(y, x, tw, tid);
    fstage<4, 12,  4  >(x, y, tw, tid);
    fstage<4, 48,  1  >(y, x, tw, tid);
}

// Spectral 2:1 box downsample (exact alias identity).
__device__ __forceinline__ void derive_half(const float2* __restrict__ Z,
                                            float2* __restrict__ Zd,
                                            int M, int step, const float2* __restrict__ tw, int tid) {
    for (int k = tid; k < M; k += 256) {
        float2 a = Z[k], b = Z[k + M];
        float sr = a.x + b.x, si = a.y + b.y;
        float dr = a.x - b.x, di = a.y - b.y;
        float2 t = tw[k * step];
        float cdr = t.x * dr + t.y * di;       // conj(t) * d
        float cdi = t.x * di - t.y * dr;
        Zd[k] = make_float2(0.25f * (sr + cdr), 0.25f * (si + cdi));
    }
    __syncthreads();
}

// Whitened cross-spectrum, IN-PLACE on A (Z len N -> R[0..N/2]).
__device__ __forceinline__ void herm_inplace(float2* A, int N, float f, int tid) {
    int half = N >> 1;
    float2 rv[4]; int ws[4]; int cnt = 0;
    for (int w = tid; w <= half; w += 256) {
        int iw = (w == 0) ? 0 : N - w;
        float2 Zw = A[w], Zm = A[iw];
        float Qx = 0.5f * (Zw.x + Zm.x), Qy = 0.5f * (Zw.y - Zm.y);
        float Kx = 0.5f * (Zw.y + Zm.y), Ky = -0.5f * (Zw.x - Zm.x);
        float kmag = sqrtf(Kx * Kx + Ky * Ky);
        float sc   = f * f / (f * kmag + 1e-8f);
        rv[cnt] = make_float2((Qx * Kx + Qy * Ky) * sc, (Qy * Kx - Qx * Ky) * sc);
        ws[cnt] = w; cnt++;
    }
    __syncthreads();
    for (int i = 0; i < cnt; i++) A[ws[i]] = rv[i];
    __syncthreads();
}

// Out-of-place whitened cross-spectrum.
__device__ __forceinline__ void herm_split(const float2* __restrict__ a,
                                           float2* __restrict__ b,
                                           int N, float f, int tid) {
    int half = N >> 1;
    for (int w = tid; w <= half; w += 256) {
        int iw = (w == 0) ? 0 : N - w;
        float2 Zw = a[w], Zm = a[iw];
        float Qx = 0.5f * (Zw.x + Zm.x), Qy = 0.5f * (Zw.y - Zm.y);
        float Kx = 0.5f * (Zw.y + Zm.y), Ky = -0.5f * (Zw.x - Zm.x);
        float kmag = sqrtf(Kx * Kx + Ky * Ky);
        float sc   = f * f / (f * kmag + 1e-8f);
        b[w] = make_float2((Qx * Kx + Qy * Ky) * sc, (Qy * Kx - Qx * Ky) * sc);
    }
    __syncthreads();
}

// Packed half-length inverse input, IN-PLACE: R[0..M] -> z[0..M-1].
__device__ __forceinline__ void zbuild_inplace(float2* A, int M, int stepN,
                                               const float2* __restrict__ tw, int tid) {
    float2 zv[3]; int ms[3]; int cnt = 0;
    for (int m = tid; m < M; m += 256) {
        int im = M - m;                      // m=0 -> M
        float2 R0 = A[m];
        float2 C  = A[im];
        float Ci = (m ? -C.y : C.y);
        float Er = 0.5f * (R0.x + C.x), Ei = 0.5f * (R0.y + Ci);
        float Dr = 0.5f * (R0.x - C.x), Di = 0.5f * (R0.y - Ci);
        float2 t = tw[m * stepN];
        float wr = t.x, wi = -t.y;           // e^{+2*pi*i*m/N}
        float Or = Dr * wr - Di * wi;
        float Oi = Dr * wi + Di * wr;
        zv[cnt] = make_float2(Er - Oi, Ei + Or);
        ms[cnt] = m; cnt++;
    }
    __syncthreads();
    for (int i = 0; i < cnt; i++) A[ms[i]] = zv[i];
    __syncthreads();
}

// c[idx] from forward-FFT'd z (length M).
__device__ __forceinline__ float cval(const float2* zf, int M, int idx) {
    int p = idx >> 1;
    int q = p ? (M - p) : 0;
    float2 v = zf[q];
    return (idx & 1) ? v.y : v.x;
}

// ---------------- K2: per-(b,h,e) 3-scale whitened autocorrelation (R11) -------
// smem: A (1536 f2) + B (1536 f2) + tw (1024 f2) = 32768 B.
__global__ __launch_bounds__(256) void k2_corr() {
    extern __shared__ float2 sm2[];
    float2* A  = sm2;             // 1536
    float2* B  = sm2 + 1536;      // 1536 (Z2 at [0..767], Z4 at [768..1151])
    float2* tw = sm2 + 3072;      // 1024

    int tid = threadIdx.x;
    int bhe = blockIdx.x;
    int b = bhe >> 9;
    const float* qrow = g_qr + (size_t)bhe * LL;
    const float* krow = g_kr + (size_t)bhe * LL;

    const float TWO_PI_OVER = -6.283185307179586f / 1536.f;
    for (int t = tid; t < 1024; t += 256) {
        float s, c; __sincosf(TWO_PI_OVER * (float)t, &s, &c);
        tw[t] = make_float2(c, s);
    }
    for (int i = tid; i < LL; i += 256)
        A[i] = make_float2(qrow[i], krow[i]);
    float f = g_scal[0];
    float acc0, acc1, acc2, acc3, acc4, acc5;
    __syncthreads();

    // ---- one forward FFT of the packed signal ----
    fft1536(A, B, tw, tid);                  // Z in A

    // ---- derive downsampled spectra (exact alias identities) ----
    derive_half(A, B, 768, 1, tw, tid);      // Z2 in B[0..767]
    derive_half(B, B + 768, 384, 2, tw, tid);// Z4 in B[768..1151]

    // ======== scale 1 (N=1536, M=768) ========
    herm_inplace(A, 1536, f, tid);           // R[0..768] in A
    zbuild_inplace(A, 768, 1, tw, tid);      // z in A[0..767]
    fft768(A, A + 768, tw, tid);             // zf in A[768..1535]
    {
        float wgt = g_scal[1] * (1.f / 768.f);
        const float2* zf = A + 768;
        acc0 = wgt * cval(zf, 768, tid);
        acc1 = wgt * cval(zf, 768, tid + 256);
        acc2 = wgt * cval(zf, 768, tid + 512);
        acc3 = wgt * cval(zf, 768, tid + 768);
        acc4 = wgt * cval(zf, 768, tid + 1024);
        acc5 = wgt * cval(zf, 768, tid + 1280);
    }
    __syncthreads();

    // ======== scale 2 (N=768, M=384) ========
    herm_split(B, A, 768, f, tid);           // R[0..384] in A
    zbuild_inplace(A, 384, 2, tw, tid);      // z in A[0..383]
    fft384(A, A + 384, tw, tid);             // zf in A[384..767]
    {
        float wgt = g_scal[2] * (1.f / 384.f);
        const float2* zf = A + 384;
        const int N = 768;
        #pragma unroll
        for (int i = 0; i < 6; i++) {
            int l = tid + 256 * i;
            float coords = ((float)l + 0.5f) * 0.5f - 0.5f;
            coords = fminf(fmaxf(coords, 0.f), (float)(N - 1));
            int lo = (int)floorf(coords);
            int hi = min(lo + 1, N - 1);
            float fr = coords - (float)lo;
            float add = wgt * (cval(zf, 384, lo) * (1.f - fr) + cval(zf, 384, hi) * fr);
            if (i == 0) acc0 += add; else if (i == 1) acc1 += add;
            else if (i == 2) acc2 += add; else if (i == 3) acc3 += add;
            else if (i == 4) acc4 += add; else acc5 += add;
        }
    }
    __syncthreads();

    // ======== scale 4 (N=384, M=192) ========
    herm_split(B + 768, A, 384, f, tid);     // R[0..192] in A
    zbuild_inplace(A, 192, 4, tw, tid);      // z in A[0..191]
    fft192(A, A + 192, tw, tid);             // zf in A[0..191]
    {
        float wgt = g_scal[3] * (1.f / 192.f);
        const int N = 384;
        #pragma unroll
        for (int i = 0; i < 6; i++) {
            int l = tid + 256 * i;
            float coords = ((float)l + 0.5f) * 0.25f - 0.5f;
            coords = fminf(fmaxf(coords, 0.f), (float)(N - 1));
            int lo = (int)floorf(coords);
            int hi = min(lo + 1, N - 1);
            float fr = coords - (float)lo;
            float add = wgt * (cval(A, 192, lo) * (1.f - fr) + cval(A, 192, hi) * fr);
            if (i == 0) acc0 += add; else if (i == 1) acc1 += add;
            else if (i == 2) acc2 += add; else if (i == 3) acc3 += add;
            else if (i == 4) acc4 += add; else acc5 += add;
        }
    }

    float* gm = g_mean + b * LL;
    atomicAdd(gm + tid,        fminf(fmaxf(acc0, -10.f), 10.f));
    atomicAdd(gm + tid + 256,  fminf(fmaxf(acc1, -10.f), 10.f));
    atomicAdd(gm + tid + 512,  fminf(fmaxf(acc2, -10.f), 10.f));
    atomicAdd(gm + tid + 768,  fminf(fmaxf(acc3, -10.f), 10.f));
    atomicAdd(gm + tid + 1024, fminf(fmaxf(acc4, -10.f), 10.f));
    atomicAdd(gm + tid + 1280, fminf(fmaxf(acc5, -10.f), 10.f));
}

// ---------------- K3: per-batch top-7 + softmax (single warp, shuffle-only) ----
__global__ __launch_bounds__(32) void k3_topk() {
    int b = blockIdx.x;
    int lane = threadIdx.x;
    float v[48];
    #pragma unroll
    for (int i = 0; i < 48; i++)
        v[i] = g_mean[b * LL + lane + 32 * i] * (1.f / HE);

    float wk[TOPK]; int dk[TOPK];
    for (int it = 0; it < TOPK; it++) {
        float best = -3.0e38f; int bi = 0;
        #pragma unroll
        for (int i = 0; i < 48; i++)
            if (v[i] > best) { best = v[i]; bi = lane + 32 * i; }
        #pragma unroll
        for (int off = 16; off; off >>= 1) {
            float ov = __shfl_down_sync(0xffffffffu, best, off);
            int   oi = __shfl_down_sync(0xffffffffu, bi,   off);
            if (ov > best || (ov == best && oi < bi)) { best = ov; bi = oi; }
        }
        best = __shfl_sync(0xffffffffu, best, 0);
        bi   = __shfl_sync(0xffffffffu, bi,   0);
        wk[it] = best; dk[it] = bi;
        if ((bi & 31) == lane) v[bi >> 5] = -3.0e38f;
    }
    if (lane == 0) {
        float mx = wk[0];
        #pragma unroll
        for (int i = 1; i < TOPK; i++) mx = fmaxf(mx, wk[i]);
        float e[TOPK], ssum = 0.f;
        #pragma unroll
        for (int i = 0; i < TOPK; i++) { e[i] = expf(wk[i] - mx); ssum += e[i]; }
        #pragma unroll
        for (int i = 0; i < TOPK; i++) {
            g_nw[b * TOPK + i] = e[i] / ssum;
            g_delays[b * TOPK + i] = dk[i];
        }
    }
}

// ---------------- K4: delayed-values aggregation (R11 version) ----------------
__global__ __launch_bounds__(128) void k4_out(const float* __restrict__ vals,
                                              float* __restrict__ out) {
    int bl = blockIdx.x;
    int b = bl / LL;
    int l = bl - b * LL;
    int tid = threadIdx.x;
    float nw[TOPK]; int dl[TOPK];
    #pragma unroll
    for (int k = 0; k < TOPK; k++) {
        nw[k] = g_nw[b * TOPK + k];
        dl[k] = g_delays[b * TOPK + k];
    }
    float4 acc = make_float4(0.f, 0.f, 0.f, 0.f);
    #pragma unroll
    for (int k = 0; k < TOPK; k++) {
        int ls = l + dl[k]; if (ls >= LL) ls -= LL;
        const float4* src = (const float4*)(vals + ((size_t)b * LL + ls) * HE);
        float4 v = src[tid];
        acc.x += nw[k] * v.x; acc.y += nw[k] * v.y;
        acc.z += nw[k] * v.z; acc.w += nw[k] * v.w;
    }
    ((float4*)(out + ((size_t)b * LL + l) * HE))[tid] = acc;
}

// ---------------- launch ----------------
extern "C" void kernel_launch(void* const* d_in, const int* in_sizes, int n_in,
                              void* d_out, int out_size) {
    const float* q  = (const float*)d_in[0];
    const float* kk = (const float*)d_in[1];
    const float* v  = (const float*)d_in[2];
    const float* sw = (const float*)d_in[3];
    const float* ff = (const float*)d_in[4];

    const int K2_SMEM = 32768;  // (1536*2 + 1024) float2 = 4096*8 B

    dim3 g1(24, 64);
    k1_ln<<<g1, 256>>>(q, kk, sw, ff);
    k2_corr<<<BHE, 256, K2_SMEM>>>();
    k3_topk<<<BB, 32>>>();
    k4_out<<<BB * LL, 128>>>(v, (float*)d_out);
}